// round 10
// baseline (speedup 1.0000x reference)
#include <cuda_runtime.h>
#include <math.h>

typedef unsigned long long u64;
typedef unsigned int u32;

#define Nn 100000
#define Ee 1600000
#define Ff 128
#define NFf 4
#define Dd 64
#define NLl 3
#define Gg 128
#define NTILE 782   // ceil(Nn/128)

// ---------------- device scratch (no allocations allowed) ----------------
__device__ int   g_deg[Nn];
__device__ int   g_rowptr[Nn + 1];
__device__ int   g_fill[Nn];
__device__ int   g_bsums[256];
__device__ int   g_srcs[Ee];
__device__ int   g_eids[Ee];
__device__ float g_wcsr[NFf * Ee];
__device__ float g_stateA[NFf * Nn * Dd];
__device__ float g_stateB[NFf * Nn * Dd];
__device__ int   g_gcnt[Gg];
__device__ int   g_gstart[Gg + 1];
__device__ float g_packcv[NFf * NLl * 8192];   // [wl][k][lane] f4: wrel0,wrel1,wroot0,wroot1
__device__ float g_packrzi[NFf * 8192];        // [f][k][lane] f4: wih_r0,wih_r1,wih_z0,wih_z1
__device__ float g_packrzh[NFf * 8192];        // [f][k][lane] f4: whh_r0,whh_r1,whh_z0,whh_z1
__device__ float g_packn[NFf * 8192];          // [f][k][lane] f4: wih_n0,wih_n1,whh_n0,whh_n1

// ---------------- packed f32x2 helpers ----------------
__device__ __forceinline__ u64 ffma2(u64 a, u64 b, u64 c) {
    u64 d; asm("fma.rn.f32x2 %0,%1,%2,%3;" : "=l"(d) : "l"(a), "l"(b), "l"(c)); return d;
}
__device__ __forceinline__ u64 splat2(float v) {
    u64 d; u32 r = __float_as_uint(v);
    asm("mov.b64 %0,{%1,%2};" : "=l"(d) : "r"(r), "r"(r)); return d;
}
__device__ __forceinline__ float2 unpk(u64 v) {
    u32 lo, hi; asm("mov.b64 {%0,%1},%2;" : "=r"(lo), "=r"(hi) : "l"(v));
    return make_float2(__uint_as_float(lo), __uint_as_float(hi));
}
__device__ __forceinline__ u64 pk(float a, float b) {
    u64 d;
    asm("mov.b64 %0,{%1,%2};" : "=l"(d) : "r"(__float_as_uint(a)), "r"(__float_as_uint(b)));
    return d;
}
__device__ __forceinline__ float sigm(float v) { return 1.f / (1.f + __expf(-v)); }
__device__ __forceinline__ float tanh_f(float v) { return 2.f / (1.f + __expf(-2.f * v)) - 1.f; }

// load 4 node-pairs (32B) via 2 LDS.128 broadcasts
#define LOADP4(dst, base) do { \
    const float4* _p4 = (const float4*)(base); \
    float4 _a = _p4[0], _b = _p4[1]; \
    dst[0] = pk(_a.x, _a.y); dst[1] = pk(_a.z, _a.w); \
    dst[2] = pk(_b.x, _b.y); dst[3] = pk(_b.z, _b.w); \
} while (0)

// ---------------- CSR build ----------------
__global__ void k_zero() {
    int i = blockIdx.x * blockDim.x + threadIdx.x;
    if (i < Nn) g_deg[i] = 0;
    if (i < Gg) g_gcnt[i] = 0;
}

__global__ void k_hist(const int* __restrict__ dst, const int* __restrict__ batch) {
    int i = blockIdx.x * blockDim.x + threadIdx.x;
    if (i < Ee) atomicAdd(&g_deg[dst[i]], 1);
    if (i < Nn) atomicAdd(&g_gcnt[batch[i]], 1);
}

__global__ void k_scan1() {
    __shared__ int tmp[1024];
    int i = blockIdx.x * 1024 + threadIdx.x;
    int v = (i < Nn) ? g_deg[i] : 0;
    tmp[threadIdx.x] = v;
    __syncthreads();
    for (int off = 1; off < 1024; off <<= 1) {
        int t = 0;
        if (threadIdx.x >= off) t = tmp[threadIdx.x - off];
        __syncthreads();
        if (threadIdx.x >= off) tmp[threadIdx.x] += t;
        __syncthreads();
    }
    if (i < Nn) g_rowptr[i + 1] = tmp[threadIdx.x];
    if (threadIdx.x == 1023) g_bsums[blockIdx.x] = tmp[1023];
}

__global__ void k_scan2(int nb) {
    if (threadIdx.x == 0 && blockIdx.x == 0) {
        int run = 0;
        for (int b = 0; b < nb; b++) { int v = g_bsums[b]; g_bsums[b] = run; run += v; }
    }
}

__global__ void k_scan3() {
    int i = blockIdx.x * 1024 + threadIdx.x;
    if (i < Nn) {
        int v = g_rowptr[i + 1] + g_bsums[blockIdx.x];
        g_rowptr[i + 1] = v;
        if (i + 1 < Nn) g_fill[i + 1] = v;
    }
    if (i == 0) { g_rowptr[0] = 0; g_fill[0] = 0; }
}

__global__ void k_scatter(const int* __restrict__ src, const int* __restrict__ dst) {
    int e = blockIdx.x * blockDim.x + threadIdx.x;
    if (e < Ee) {
        int d = dst[e];
        int p = atomicAdd(&g_fill[d], 1);
        g_srcs[p] = src[e];
        g_eids[p] = e;
    }
}

__global__ void k_sortseg() {
    int n = blockIdx.x * blockDim.x + threadIdx.x;
    if (n >= Nn) return;
    int b = g_rowptr[n], e = g_rowptr[n + 1];
    for (int i = b + 1; i < e; i++) {
        int ke = g_eids[i], ks = g_srcs[i];
        int j = i - 1;
        while (j >= b && g_eids[j] > ke) {
            g_eids[j + 1] = g_eids[j];
            g_srcs[j + 1] = g_srcs[j];
            j--;
        }
        g_eids[j + 1] = ke;
        g_srcs[j + 1] = ks;
    }
}

__global__ void k_buildw(const float* __restrict__ att) {
    int j = blockIdx.x * blockDim.x + threadIdx.x;
    if (j < Ee) {
        int e = g_eids[j];
#pragma unroll
        for (int f = 0; f < NFf; f++) g_wcsr[f * Ee + j] = att[f * Ee + e];
    }
}

__global__ void k_gscan() {
    if (threadIdx.x == 0 && blockIdx.x == 0) {
        int run = 0;
        for (int g = 0; g < Gg; g++) { g_gstart[g] = run; run += g_gcnt[g]; }
        g_gstart[Gg] = run;
    }
}

// ---------------- weight pre-pack ----------------
__global__ void k_pack(const float* __restrict__ Wrel, const float* __restrict__ Wroot,
                       const float* __restrict__ Wih, const float* __restrict__ Whh) {
    int i = blockIdx.x * blockDim.x + threadIdx.x;
    if (i < 24576) {           // conv: 12 layers x 2048
        int wl = i >> 11, r = i & 2047, k = r >> 5, l = r & 31;
        const float* A = Wrel + wl * 4096;
        const float* B = Wroot + wl * 4096;
        ((float4*)g_packcv)[i] = make_float4(A[k * 64 + 2 * l], A[k * 64 + 2 * l + 1],
                                             B[k * 64 + 2 * l], B[k * 64 + 2 * l + 1]);
        return;
    }
    int j = i - 24576;
    if (j < 8192) {            // rz input weights
        int f = j >> 11, r = j & 2047, k = r >> 5, l = r & 31;
        const float* I = Wih + f * 12288;
        ((float4*)g_packrzi)[j] = make_float4(I[(2 * l) * 64 + k], I[(2 * l + 1) * 64 + k],
                                              I[(64 + 2 * l) * 64 + k], I[(64 + 2 * l + 1) * 64 + k]);
        return;
    }
    j -= 8192;
    if (j < 8192) {            // rz hidden weights
        int f = j >> 11, r = j & 2047, k = r >> 5, l = r & 31;
        const float* H = Whh + f * 12288;
        ((float4*)g_packrzh)[j] = make_float4(H[(2 * l) * 64 + k], H[(2 * l + 1) * 64 + k],
                                              H[(64 + 2 * l) * 64 + k], H[(64 + 2 * l + 1) * 64 + k]);
        return;
    }
    j -= 8192;
    if (j < 8192) {            // n gate weights (ih + hh)
        int f = j >> 11, r = j & 2047, k = r >> 5, l = r & 31;
        const float* I = Wih + f * 12288;
        const float* H = Whh + f * 12288;
        ((float4*)g_packn)[j] = make_float4(I[(128 + 2 * l) * 64 + k], I[(128 + 2 * l + 1) * 64 + k],
                                            H[(128 + 2 * l) * 64 + k], H[(128 + 2 * l + 1) * 64 + k]);
    }
}

// ---------------- lin (all factors, 8 nodes/warp, 16 warps) ----------------
#define LIN_SHM ((8192 + 64 + 16 * 1280) * 4)
__global__ __launch_bounds__(512, 1) void k_lin(const float* __restrict__ x,
                                                const float* __restrict__ W_all,
                                                const float* __restrict__ b_all,
                                                float* __restrict__ out_base) {
    extern __shared__ float sh[];
    float* sW = sh;
    float* sb = sW + 8192;
    float* sX = sb + 64;
    int f = blockIdx.x & 3;
    int fslot = blockIdx.x >> 2;
    int nslot = gridDim.x >> 2;
    const float* W = W_all + f * Ff * Dd;
    const float* b = b_all + f * Dd;
    float* out = out_base + f * Nn * Dd;

    int tid = threadIdx.x;
    for (int i = tid; i < 8192; i += 512) sW[i] = W[i];
    if (tid < 64) sb[tid] = b[tid];
    __syncthreads();
    int warp = tid >> 5, lane = tid & 31;
    int d0 = 2 * lane;
    int nt = lane >> 2, cg = lane & 3;
    float* sXw = sX + warp * 1280;
    float bc0 = sb[d0], bc1 = sb[d0 + 1];

    for (int t = fslot; t < NTILE; t += nslot) {
        int n0 = t * 128 + warp * 8;
        if (n0 >= Nn) continue;
        {
            int n = n0 + nt;
            bool v = n < Nn;
            const float4* xr = (const float4*)(x + (v ? n : 0) * Ff) + cg * 8;
#pragma unroll
            for (int q = 0; q < 8; q++) {
                float4 tv = v ? xr[q] : make_float4(0, 0, 0, 0);
                int c = cg * 32 + q * 4;
                sXw[(c + 0) * 10 + nt] = tv.x;
                sXw[(c + 1) * 10 + nt] = tv.y;
                sXw[(c + 2) * 10 + nt] = tv.z;
                sXw[(c + 3) * 10 + nt] = tv.w;
            }
        }
        __syncwarp();
        u64 acc[4][2];
#pragma unroll
        for (int p = 0; p < 4; p++) { acc[p][0] = 0ull; acc[p][1] = 0ull; }
#pragma unroll 4
        for (int k = 0; k < Ff; k++) {
            float2 w = *(const float2*)(sW + k * 64 + d0);
            u64 sw0 = splat2(w.x), sw1 = splat2(w.y);
            const u64* xp = (const u64*)(sXw + k * 10);
#pragma unroll
            for (int p = 0; p < 4; p++) {
                u64 xv = xp[p];
                acc[p][0] = ffma2(xv, sw0, acc[p][0]);
                acc[p][1] = ffma2(xv, sw1, acc[p][1]);
            }
        }
#pragma unroll
        for (int p = 0; p < 4; p++) {
            float2 a0 = unpk(acc[p][0]), a1 = unpk(acc[p][1]);
            int na = n0 + 2 * p, nb = na + 1;
            if (na < Nn) *(float2*)(out + na * 64 + d0) = make_float2(a0.x + bc0, a1.x + bc1);
            if (nb < Nn) *(float2*)(out + nb * 64 + d0) = make_float2(a0.y + bc0, a1.y + bc1);
        }
        __syncwarp();
    }
}

// ---------------- fused layer (all factors, 8 nodes/warp, 16 warps) ----------------
// stage stride 12 floats (48B, 16B-aligned) so acts load as LDS.128
#define LAYER_SHM ((8192 * 4 + 16 * 1536) * 4)
__global__ __launch_bounds__(512, 1) void k_layer(const float* __restrict__ in_base,
                                                  float* __restrict__ out_base,
                                                  int layer,
                                                  const float* __restrict__ brel_all,
                                                  const float* __restrict__ bih_all,
                                                  const float* __restrict__ bhh_all) {
    extern __shared__ float sh[];
    float* sWcv  = sh;               // 8192: [k][lane] f4
    float* sWrzi = sWcv + 8192;      // 8192
    float* sWrzh = sWrzi + 8192;     // 8192
    float* sWn   = sWrzh + 8192;     // 8192
    float* sStage = sWn + 8192;      // 16 warps * 1536

    int f = blockIdx.x & 3;
    int fslot = blockIdx.x >> 2;
    int nslot = gridDim.x >> 2;
    int wl = f * NLl + layer;
    const float* in_state = in_base + f * Nn * Dd;
    float* out_state = out_base + f * Nn * Dd;
    const float* wfp = g_wcsr + f * Ee;

    int tid = threadIdx.x;
    {
        const float4* p0 = (const float4*)(g_packcv + wl * 8192);
        const float4* p1 = (const float4*)(g_packrzi + f * 8192);
        const float4* p2 = (const float4*)(g_packrzh + f * 8192);
        const float4* p3 = (const float4*)(g_packn + f * 8192);
        float4* d0_ = (float4*)sWcv;
        float4* d1_ = (float4*)sWrzi;
        float4* d2_ = (float4*)sWrzh;
        float4* d3_ = (float4*)sWn;
        for (int i = tid; i < 2048; i += 512) {
            d0_[i] = p0[i]; d1_[i] = p1[i]; d2_[i] = p2[i]; d3_[i] = p3[i];
        }
    }
    __syncthreads();

    int warp = tid >> 5, lane = tid & 31;
    int d0 = 2 * lane;
    int nt = lane >> 2, cg = lane & 3;
    float* sIn = sStage + warp * 1536;   // [col][12]
    float* sA  = sIn + 768;              // agg, then m

    const float* brel = brel_all + wl * 64;
    float br0 = brel[d0], br1 = brel[d0 + 1];
    float bi_[6], bh_[6];
#pragma unroll
    for (int g = 0; g < 3; g++) {
        bi_[2 * g] = bih_all[f * 192 + 64 * g + d0];
        bi_[2 * g + 1] = bih_all[f * 192 + 64 * g + d0 + 1];
        bh_[2 * g] = bhh_all[f * 192 + 64 * g + d0];
        bh_[2 * g + 1] = bhh_all[f * 192 + 64 * g + d0 + 1];
    }

    for (int t = fslot; t < NTILE; t += nslot) {
        int n0 = t * 128 + warp * 8;
        if (n0 >= Nn) continue;

        // ---- stage h + edge aggregation (unroll-2, MLP 8), transposed [col][node] ----
        {
            int n = n0 + nt;
            bool v = n < Nn;
            const float4* xr = (const float4*)(in_state + (v ? n : 0) * 64) + cg * 4;
            float acc16[16];
#pragma unroll
            for (int q = 0; q < 4; q++) {
                float4 tv = v ? xr[q] : make_float4(0, 0, 0, 0);
                int c = cg * 16 + q * 4;
                sIn[(c + 0) * 12 + nt] = tv.x;
                sIn[(c + 1) * 12 + nt] = tv.y;
                sIn[(c + 2) * 12 + nt] = tv.z;
                sIn[(c + 3) * 12 + nt] = tv.w;
            }
#pragma unroll
            for (int i = 0; i < 16; i++) acc16[i] = 0.f;
            if (v) {
                int beg = g_rowptr[n], end = g_rowptr[n + 1];
                int j = beg;
                for (; j + 2 <= end; j += 2) {
                    int s0 = g_srcs[j], s1 = g_srcs[j + 1];
                    float w0 = wfp[j], w1 = wfp[j + 1];
                    const float4* r0p = (const float4*)(in_state + s0 * 64) + cg * 4;
                    const float4* r1p = (const float4*)(in_state + s1 * 64) + cg * 4;
                    float4 a0 = r0p[0], a1 = r0p[1], a2 = r0p[2], a3 = r0p[3];
                    float4 b0 = r1p[0], b1 = r1p[1], b2 = r1p[2], b3 = r1p[3];
                    // edge j first (original order), then edge j+1
                    acc16[0]  += w0 * a0.x; acc16[1]  += w0 * a0.y; acc16[2]  += w0 * a0.z; acc16[3]  += w0 * a0.w;
                    acc16[4]  += w0 * a1.x; acc16[5]  += w0 * a1.y; acc16[6]  += w0 * a1.z; acc16[7]  += w0 * a1.w;
                    acc16[8]  += w0 * a2.x; acc16[9]  += w0 * a2.y; acc16[10] += w0 * a2.z; acc16[11] += w0 * a2.w;
                    acc16[12] += w0 * a3.x; acc16[13] += w0 * a3.y; acc16[14] += w0 * a3.z; acc16[15] += w0 * a3.w;
                    acc16[0]  += w1 * b0.x; acc16[1]  += w1 * b0.y; acc16[2]  += w1 * b0.z; acc16[3]  += w1 * b0.w;
                    acc16[4]  += w1 * b1.x; acc16[5]  += w1 * b1.y; acc16[6]  += w1 * b1.z; acc16[7]  += w1 * b1.w;
                    acc16[8]  += w1 * b2.x; acc16[9]  += w1 * b2.y; acc16[10] += w1 * b2.z; acc16[11] += w1 * b2.w;
                    acc16[12] += w1 * b3.x; acc16[13] += w1 * b3.y; acc16[14] += w1 * b3.z; acc16[15] += w1 * b3.w;
                }
                if (j < end) {
                    int s = g_srcs[j];
                    float w = wfp[j];
                    const float4* sr = (const float4*)(in_state + s * 64) + cg * 4;
#pragma unroll
                    for (int q = 0; q < 4; q++) {
                        float4 tv = sr[q];
                        acc16[q * 4 + 0] += w * tv.x;
                        acc16[q * 4 + 1] += w * tv.y;
                        acc16[q * 4 + 2] += w * tv.z;
                        acc16[q * 4 + 3] += w * tv.w;
                    }
                }
            }
#pragma unroll
            for (int i = 0; i < 16; i++) sA[(cg * 16 + i) * 12 + nt] = acc16[i];
        }
        __syncwarp();

        // ---- GraphConv: m = relu(agg@Wrel + brel + h@Wroot) ----
        {
            u64 am[4][2];
#pragma unroll
            for (int p = 0; p < 4; p++) { am[p][0] = 0ull; am[p][1] = 0ull; }
#pragma unroll 2
            for (int k = 0; k < 64; k++) {
                float4 w = ((const float4*)sWcv)[k * 32 + lane];
                u64 sr0 = splat2(w.x), sr1 = splat2(w.y);
                u64 so0 = splat2(w.z), so1 = splat2(w.w);
                u64 av[4], hvv[4];
                LOADP4(av, sA + k * 12);
                LOADP4(hvv, sIn + k * 12);
#pragma unroll
                for (int p = 0; p < 4; p++) {
                    am[p][0] = ffma2(av[p], sr0, am[p][0]);
                    am[p][0] = ffma2(hvv[p], so0, am[p][0]);
                    am[p][1] = ffma2(av[p], sr1, am[p][1]);
                    am[p][1] = ffma2(hvv[p], so1, am[p][1]);
                }
            }
            __syncwarp();   // done reading sA (agg) before overwrite with m
#pragma unroll
            for (int p = 0; p < 4; p++) {
                float2 c0 = unpk(am[p][0]), c1 = unpk(am[p][1]);
                float m00 = fmaxf(c0.x + br0, 0.f);
                float m10 = fmaxf(c0.y + br0, 0.f);
                float m01 = fmaxf(c1.x + br1, 0.f);
                float m11 = fmaxf(c1.y + br1, 0.f);
                *(u64*)(sA + d0 * 12 + 2 * p)       = pk(m00, m10);
                *(u64*)(sA + (d0 + 1) * 12 + 2 * p) = pk(m01, m11);
            }
        }
        __syncwarp();

        // ---- GRU pass 1: r and z gates ----
        u64 rp[8], zp[8];
        {
            u64 arz[4][4], hrz[4][4];
#pragma unroll
            for (int p = 0; p < 4; p++)
#pragma unroll
                for (int g = 0; g < 4; g++) { arz[p][g] = 0ull; hrz[p][g] = 0ull; }
#pragma unroll 1
            for (int k = 0; k < 64; k++) {
                float4 wi = ((const float4*)sWrzi)[k * 32 + lane];
                float4 wh = ((const float4*)sWrzh)[k * 32 + lane];
                u64 sir0 = splat2(wi.x), sir1 = splat2(wi.y);
                u64 siz0 = splat2(wi.z), siz1 = splat2(wi.w);
                u64 shr0 = splat2(wh.x), shr1 = splat2(wh.y);
                u64 shz0 = splat2(wh.z), shz1 = splat2(wh.w);
                u64 mv[4], hvv[4];
                LOADP4(mv, sA + k * 12);
                LOADP4(hvv, sIn + k * 12);
#pragma unroll
                for (int p = 0; p < 4; p++) {
                    arz[p][0] = ffma2(mv[p], sir0, arz[p][0]);
                    arz[p][1] = ffma2(mv[p], sir1, arz[p][1]);
                    arz[p][2] = ffma2(mv[p], siz0, arz[p][2]);
                    arz[p][3] = ffma2(mv[p], siz1, arz[p][3]);
                    hrz[p][0] = ffma2(hvv[p], shr0, hrz[p][0]);
                    hrz[p][1] = ffma2(hvv[p], shr1, hrz[p][1]);
                    hrz[p][2] = ffma2(hvv[p], shz0, hrz[p][2]);
                    hrz[p][3] = ffma2(hvv[p], shz1, hrz[p][3]);
                }
            }
#pragma unroll
            for (int p = 0; p < 4; p++) {
                float2 vir0 = unpk(arz[p][0]), vir1 = unpk(arz[p][1]);
                float2 viz0 = unpk(arz[p][2]), viz1 = unpk(arz[p][3]);
                float2 vhr0 = unpk(hrz[p][0]), vhr1 = unpk(hrz[p][1]);
                float2 vhz0 = unpk(hrz[p][2]), vhz1 = unpk(hrz[p][3]);
                float ra0 = sigm(vir0.x + bi_[0] + vhr0.x + bh_[0]);
                float rb0 = sigm(vir0.y + bi_[0] + vhr0.y + bh_[0]);
                float ra1 = sigm(vir1.x + bi_[1] + vhr1.x + bh_[1]);
                float rb1 = sigm(vir1.y + bi_[1] + vhr1.y + bh_[1]);
                float za0 = sigm(viz0.x + bi_[2] + vhz0.x + bh_[2]);
                float zb0 = sigm(viz0.y + bi_[2] + vhz0.y + bh_[2]);
                float za1 = sigm(viz1.x + bi_[3] + vhz1.x + bh_[3]);
                float zb1 = sigm(viz1.y + bi_[3] + vhz1.y + bh_[3]);
                rp[2 * p] = pk(ra0, rb0); rp[2 * p + 1] = pk(ra1, rb1);
                zp[2 * p] = pk(za0, zb0); zp[2 * p + 1] = pk(za1, zb1);
            }
        }

        // ---- GRU pass 2: n gate + blend + store ----
        {
            u64 an_[4][2], hn_[4][2];
#pragma unroll
            for (int p = 0; p < 4; p++) { an_[p][0] = 0ull; an_[p][1] = 0ull; hn_[p][0] = 0ull; hn_[p][1] = 0ull; }
#pragma unroll 2
            for (int k = 0; k < 64; k++) {
                float4 w = ((const float4*)sWn)[k * 32 + lane];
                u64 sin0 = splat2(w.x), sin1 = splat2(w.y);
                u64 shn0 = splat2(w.z), shn1 = splat2(w.w);
                u64 mv[4], hvv[4];
                LOADP4(mv, sA + k * 12);
                LOADP4(hvv, sIn + k * 12);
#pragma unroll
                for (int p = 0; p < 4; p++) {
                    an_[p][0] = ffma2(mv[p], sin0, an_[p][0]);
                    an_[p][1] = ffma2(mv[p], sin1, an_[p][1]);
                    hn_[p][0] = ffma2(hvv[p], shn0, hn_[p][0]);
                    hn_[p][1] = ffma2(hvv[p], shn1, hn_[p][1]);
                }
            }
#pragma unroll
            for (int p = 0; p < 4; p++) {
                float2 vin0 = unpk(an_[p][0]), vin1 = unpk(an_[p][1]);
                float2 vhn0 = unpk(hn_[p][0]), vhn1 = unpk(hn_[p][1]);
                float2 r0 = unpk(rp[2 * p]), r1 = unpk(rp[2 * p + 1]);
                float2 z0 = unpk(zp[2 * p]), z1 = unpk(zp[2 * p + 1]);
                float2 h0 = unpk(*(const u64*)(sIn + d0 * 12 + 2 * p));
                float2 h1 = unpk(*(const u64*)(sIn + (d0 + 1) * 12 + 2 * p));
                float na0 = tanh_f(vin0.x + bi_[4] + r0.x * (vhn0.x + bh_[4]));
                float nb0 = tanh_f(vin0.y + bi_[4] + r0.y * (vhn0.y + bh_[4]));
                float na1 = tanh_f(vin1.x + bi_[5] + r1.x * (vhn1.x + bh_[5]));
                float nb1 = tanh_f(vin1.y + bi_[5] + r1.y * (vhn1.y + bh_[5]));
                float oa0 = (1.f - z0.x) * na0 + z0.x * h0.x;
                float ob0 = (1.f - z0.y) * nb0 + z0.y * h0.y;
                float oa1 = (1.f - z1.x) * na1 + z1.x * h1.x;
                float ob1 = (1.f - z1.y) * nb1 + z1.y * h1.y;
                int na = n0 + 2 * p, nb = na + 1;
                if (na < Nn) *(float2*)(out_state + na * 64 + d0) = make_float2(oa0, oa1);
                if (nb < Nn) *(float2*)(out_state + nb * 64 + d0) = make_float2(ob0, ob1);
            }
        }
        __syncwarp();
    }
}

// ---------------- global mean pool ----------------
__global__ void k_pool(const float* __restrict__ feats, float* __restrict__ out) {
    int g = blockIdx.x, f = blockIdx.y, d = threadIdx.x;  // blockDim = 64
    int s = g_gstart[g], e = g_gstart[g + 1];
    const float* base = feats + f * Nn * Dd;
    float s0 = 0.f, s1 = 0.f, s2 = 0.f, s3 = 0.f;
    int i = s;
    for (; i + 3 < e; i += 4) {
        s0 += base[i * Dd + d];
        s1 += base[(i + 1) * Dd + d];
        s2 += base[(i + 2) * Dd + d];
        s3 += base[(i + 3) * Dd + d];
    }
    for (; i < e; i++) s0 += base[i * Dd + d];
    float sum = (s0 + s1) + (s2 + s3);
    int cnt = e - s;
    if (cnt < 1) cnt = 1;
    out[(f * Gg + g) * Dd + d] = sum / (float)cnt;
}

// ---------------- host ----------------
extern "C" void kernel_launch(void* const* d_in, const int* in_sizes, int n_in,
                              void* d_out, int out_size) {
    const float* x     = (const float*)d_in[0];
    const int*   ei    = (const int*)d_in[1];
    const float* att   = (const float*)d_in[2];
    const int*   batch = (const int*)d_in[3];
    const float* lin_W = (const float*)d_in[4];
    const float* lin_b = (const float*)d_in[5];
    const float* Wrel  = (const float*)d_in[6];
    const float* brel  = (const float*)d_in[7];
    const float* Wroot = (const float*)d_in[8];
    const float* Wih   = (const float*)d_in[9];
    const float* Whh   = (const float*)d_in[10];
    const float* bih   = (const float*)d_in[11];
    const float* bhh   = (const float*)d_in[12];

    float* out = (float*)d_out;
    float* feats = out + NFf * Gg * Dd;
    const int* srcp = ei;
    const int* dstp = ei + Ee;

    int sm = 148;
    cudaDeviceGetAttribute(&sm, cudaDevAttrMultiProcessorCount, 0);
    int grid = (sm / 4) * 4;
    if (grid < 4) grid = 4;

    cudaFuncSetAttribute(k_layer, cudaFuncAttributeMaxDynamicSharedMemorySize, LAYER_SHM);
    cudaFuncSetAttribute(k_lin, cudaFuncAttributeMaxDynamicSharedMemorySize, LIN_SHM);

    void *pa, *pb;
    cudaGetSymbolAddress(&pa, g_stateA);
    cudaGetSymbolAddress(&pb, g_stateB);
    float* A = (float*)pa;
    float* B = (float*)pb;

    const int NB = (Nn + 1023) / 1024;

    k_zero<<<(Nn + 255) / 256, 256>>>();
    k_hist<<<(Ee + 255) / 256, 256>>>(dstp, batch);
    k_scan1<<<NB, 1024>>>();
    k_scan2<<<1, 32>>>(NB);
    k_scan3<<<NB, 1024>>>();
    k_scatter<<<(Ee + 255) / 256, 256>>>(srcp, dstp);
    k_sortseg<<<(Nn + 127) / 128, 128>>>();
    k_buildw<<<(Ee + 255) / 256, 256>>>(att);
    k_gscan<<<1, 32>>>();
    k_pack<<<(24576 + 3 * 8192 + 255) / 256, 256>>>(Wrel, Wroot, Wih, Whh);

    k_lin<<<grid, 512, LIN_SHM>>>(x, lin_W, lin_b, A);
    k_layer<<<grid, 512, LAYER_SHM>>>(A, B, 0, brel, bih, bhh);
    k_layer<<<grid, 512, LAYER_SHM>>>(B, A, 1, brel, bih, bhh);
    k_layer<<<grid, 512, LAYER_SHM>>>(A, feats, 2, brel, bih, bhh);
    k_pool<<<dim3(Gg, NFf), 64>>>(feats, out);
}

// round 11
// speedup vs baseline: 1.2036x; 1.2036x over previous
#include <cuda_runtime.h>
#include <cuda_bf16.h>
#include <math.h>

typedef unsigned long long u64;
typedef unsigned int u32;

#define Nn 100000
#define Ee 1600000
#define Ff 128
#define NFf 4
#define Dd 64
#define NLl 3
#define Gg 128
#define NTILE 782   // ceil(Nn/128)

// ---------------- device scratch (no allocations allowed) ----------------
__device__ int   g_deg[Nn];
__device__ int   g_rowptr[Nn + 1];
__device__ int   g_fill[Nn];
__device__ int   g_bsums[256];
__device__ int   g_srcs[Ee];
__device__ int   g_eids[Ee];
__device__ float g_wcsr[NFf * Ee];
__device__ float g_stateA[NFf * Nn * Dd];
__device__ float g_stateB[NFf * Nn * Dd];
__device__ int   g_gcnt[Gg];
__device__ int   g_gstart[Gg + 1];
// fragment-packed bf16 weights (uint2 per lane-fragment)
__device__ uint2 g_pkconv[12 * 4096];   // [wl][mat:relH,relL,rootH,rootL][ks4][nt8][lane32]
__device__ uint2 g_pkgru[4 * 12288];    // [f][ihH2048,ihL2048,hhH2048,hhL2048,inH1024,inL1024,hnH1024,hnL1024]

// ---------------- helpers ----------------
__device__ __forceinline__ u64 ffma2(u64 a, u64 b, u64 c) {
    u64 d; asm("fma.rn.f32x2 %0,%1,%2,%3;" : "=l"(d) : "l"(a), "l"(b), "l"(c)); return d;
}
__device__ __forceinline__ u64 splat2(float v) {
    u64 d; u32 r = __float_as_uint(v);
    asm("mov.b64 %0,{%1,%2};" : "=l"(d) : "r"(r), "r"(r)); return d;
}
__device__ __forceinline__ float2 unpk(u64 v) {
    u32 lo, hi; asm("mov.b64 {%0,%1},%2;" : "=r"(lo), "=r"(hi) : "l"(v));
    return make_float2(__uint_as_float(lo), __uint_as_float(hi));
}
__device__ __forceinline__ float sigm(float v) { return 1.f / (1.f + __expf(-v)); }
__device__ __forceinline__ float tanh_f(float v) { return 2.f / (1.f + __expf(-2.f * v)) - 1.f; }

__device__ __forceinline__ u32 smem_u32(const void* p) {
    u32 a;
    asm("{ .reg .u64 t; cvta.to.shared.u64 t, %1; cvt.u32.u64 %0, t; }" : "=r"(a) : "l"(p));
    return a;
}

// split (a0,a1) fp32 -> hi bf16x2 word + lo residual bf16x2 word
__device__ __forceinline__ void split2(float a0, float a1, u32& hi, u32& lo) {
    __nv_bfloat16 h0 = __float2bfloat16(a0), h1 = __float2bfloat16(a1);
    __nv_bfloat162 hp = __halves2bfloat162(h0, h1);
    float r0 = a0 - __bfloat162float(h0);
    float r1 = a1 - __bfloat162float(h1);
    __nv_bfloat162 lp = __floats2bfloat162_rn(r0, r1);
    hi = *(u32*)&hp; lo = *(u32*)&lp;
}

// pack two elems as bf16x2, hi or lo split selected
__device__ __forceinline__ u32 pkbf(float a, float b, bool lo) {
    __nv_bfloat16 ah = __float2bfloat16(a), bh = __float2bfloat16(b);
    if (lo) {
        ah = __float2bfloat16(a - __bfloat162float(ah));
        bh = __float2bfloat16(b - __bfloat162float(bh));
    }
    __nv_bfloat162 p = __halves2bfloat162(ah, bh);
    return *(u32*)&p;
}

__device__ __forceinline__ uint4 ldm(u32 addr) {
    uint4 r;
    asm volatile("ldmatrix.sync.aligned.m8n8.x4.shared.b16 {%0,%1,%2,%3}, [%4];"
        : "=r"(r.x), "=r"(r.y), "=r"(r.z), "=r"(r.w) : "r"(addr));
    return r;
}
__device__ __forceinline__ void mmaf(float d[4], uint4 a, uint2 b) {
    asm volatile("mma.sync.aligned.m16n8k16.row.col.f32.bf16.bf16.f32 "
        "{%0,%1,%2,%3}, {%4,%5,%6,%7}, {%8,%9}, {%0,%1,%2,%3};"
        : "+f"(d[0]), "+f"(d[1]), "+f"(d[2]), "+f"(d[3])
        : "r"(a.x), "r"(a.y), "r"(a.z), "r"(a.w), "r"(b.x), "r"(b.y));
}

// ---------------- CSR build ----------------
__global__ void k_zero() {
    int i = blockIdx.x * blockDim.x + threadIdx.x;
    if (i < Nn) g_deg[i] = 0;
    if (i < Gg) g_gcnt[i] = 0;
}

__global__ void k_hist(const int* __restrict__ dst, const int* __restrict__ batch) {
    int i = blockIdx.x * blockDim.x + threadIdx.x;
    if (i < Ee) atomicAdd(&g_deg[dst[i]], 1);
    if (i < Nn) atomicAdd(&g_gcnt[batch[i]], 1);
}

__global__ void k_scan1() {
    __shared__ int tmp[1024];
    int i = blockIdx.x * 1024 + threadIdx.x;
    int v = (i < Nn) ? g_deg[i] : 0;
    tmp[threadIdx.x] = v;
    __syncthreads();
    for (int off = 1; off < 1024; off <<= 1) {
        int t = 0;
        if (threadIdx.x >= off) t = tmp[threadIdx.x - off];
        __syncthreads();
        if (threadIdx.x >= off) tmp[threadIdx.x] += t;
        __syncthreads();
    }
    if (i < Nn) g_rowptr[i + 1] = tmp[threadIdx.x];
    if (threadIdx.x == 1023) g_bsums[blockIdx.x] = tmp[1023];
}

__global__ void k_scan2(int nb) {
    if (threadIdx.x == 0 && blockIdx.x == 0) {
        int run = 0;
        for (int b = 0; b < nb; b++) { int v = g_bsums[b]; g_bsums[b] = run; run += v; }
    }
}

__global__ void k_scan3() {
    int i = blockIdx.x * 1024 + threadIdx.x;
    if (i < Nn) {
        int v = g_rowptr[i + 1] + g_bsums[blockIdx.x];
        g_rowptr[i + 1] = v;
        if (i + 1 < Nn) g_fill[i + 1] = v;
    }
    if (i == 0) { g_rowptr[0] = 0; g_fill[0] = 0; }
}

__global__ void k_scatter(const int* __restrict__ src, const int* __restrict__ dst) {
    int e = blockIdx.x * blockDim.x + threadIdx.x;
    if (e < Ee) {
        int d = dst[e];
        int p = atomicAdd(&g_fill[d], 1);
        g_srcs[p] = src[e];
        g_eids[p] = e;
    }
}

__global__ void k_sortseg() {
    int n = blockIdx.x * blockDim.x + threadIdx.x;
    if (n >= Nn) return;
    int b = g_rowptr[n], e = g_rowptr[n + 1];
    for (int i = b + 1; i < e; i++) {
        int ke = g_eids[i], ks = g_srcs[i];
        int j = i - 1;
        while (j >= b && g_eids[j] > ke) {
            g_eids[j + 1] = g_eids[j];
            g_srcs[j + 1] = g_srcs[j];
            j--;
        }
        g_eids[j + 1] = ke;
        g_srcs[j + 1] = ks;
    }
}

__global__ void k_buildw(const float* __restrict__ att) {
    int j = blockIdx.x * blockDim.x + threadIdx.x;
    if (j < Ee) {
        int e = g_eids[j];
#pragma unroll
        for (int f = 0; f < NFf; f++) g_wcsr[f * Ee + j] = att[f * Ee + e];
    }
}

__global__ void k_gscan() {
    if (threadIdx.x == 0 && blockIdx.x == 0) {
        int run = 0;
        for (int g = 0; g < Gg; g++) { g_gstart[g] = run; run += g_gcnt[g]; }
        g_gstart[Gg] = run;
    }
}

// ---------------- weight pre-pack: bf16 hi/lo in mma B-fragment lane order ----------------
// B fragment (16x8, col): lane l holds b.x = {B[k0+2s][n], B[k0+2s+1][n]}, b.y = {B[k0+8+2s][n], B[k0+9+2s][n]}
// with s = l&3, n = nt*8 + (l>>2), k0 = ks*16.
__global__ void k_pack(const float* __restrict__ Wrel, const float* __restrict__ Wroot,
                       const float* __restrict__ Wih, const float* __restrict__ Whh) {
    int i = blockIdx.x * blockDim.x + threadIdx.x;
    if (i >= 98304) return;
    float v00, v01, v10, v11;
    bool lo;
    uint2* dst;
    if (i < 49152) {
        int wl = i >> 12;
        int r = i & 4095;
        int mat = r >> 10;          // 0 relH, 1 relL, 2 rootH, 3 rootL
        int fr = r & 1023;
        int ks = fr >> 8, nt = (fr >> 5) & 7, lane = fr & 31;
        int s = lane & 3, n = nt * 8 + (lane >> 2);
        int k0 = ks * 16 + 2 * s;
        const float* Wm = ((mat >= 2) ? Wroot : Wrel) + wl * 4096;  // [k][d] -> B[k][n]
        v00 = Wm[k0 * 64 + n];       v01 = Wm[(k0 + 1) * 64 + n];
        v10 = Wm[(k0 + 8) * 64 + n]; v11 = Wm[(k0 + 9) * 64 + n];
        lo = (mat & 1);
        dst = g_pkconv + i;
    } else {
        int j = i - 49152;
        int f = j / 12288;
        int r = j % 12288;
        const float* WI = Wih + f * 12288;
        const float* WH = Whh + f * 12288;
        if (r < 8192) {             // rz: ihH, ihL, hhH, hhL
            int mat = r >> 11;
            int fr = r & 2047;
            int ks = fr >> 9, nt = (fr >> 5) & 15, lane = fr & 31;
            int s = lane & 3, n = nt * 8 + (lane >> 2);    // n in 0..127 (r,z rows)
            int k0 = ks * 16 + 2 * s;
            const float* Wm = (mat >= 2) ? WH : WI;        // B[k][n] = W[n*64+k]
            v00 = Wm[n * 64 + k0];     v01 = Wm[n * 64 + k0 + 1];
            v10 = Wm[n * 64 + k0 + 8]; v11 = Wm[n * 64 + k0 + 9];
            lo = (mat & 1);
        } else {                    // n gate: inH, inL, hnH, hnL
            int rn = r - 8192;
            int mat = rn >> 10;
            int fr = rn & 1023;
            int ks = fr >> 8, nt = (fr >> 5) & 7, lane = fr & 31;
            int s = lane & 3, n = nt * 8 + (lane >> 2);
            int k0 = ks * 16 + 2 * s;
            const float* Wm = (mat >= 2) ? WH : WI;        // B[k][n] = W[(128+n)*64+k]
            v00 = Wm[(128 + n) * 64 + k0];     v01 = Wm[(128 + n) * 64 + k0 + 1];
            v10 = Wm[(128 + n) * 64 + k0 + 8]; v11 = Wm[(128 + n) * 64 + k0 + 9];
            lo = (mat & 1);
        }
        dst = g_pkgru + j;
    }
    *dst = make_uint2(pkbf(v00, v01, lo), pkbf(v10, v11, lo));
}

// ---------------- lin (FFMA champion, unchanged) ----------------
#define LIN_SHM ((8192 + 64 + 16 * 1280) * 4)
__global__ __launch_bounds__(512, 1) void k_lin(const float* __restrict__ x,
                                                const float* __restrict__ W_all,
                                                const float* __restrict__ b_all,
                                                float* __restrict__ out_base) {
    extern __shared__ float sh[];
    float* sW = sh;
    float* sb = sW + 8192;
    float* sX = sb + 64;
    int f = blockIdx.x & 3;
    int fslot = blockIdx.x >> 2;
    int nslot = gridDim.x >> 2;
    const float* W = W_all + f * Ff * Dd;
    const float* b = b_all + f * Dd;
    float* out = out_base + f * Nn * Dd;

    int tid = threadIdx.x;
    for (int i = tid; i < 8192; i += 512) sW[i] = W[i];
    if (tid < 64) sb[tid] = b[tid];
    __syncthreads();
    int warp = tid >> 5, lane = tid & 31;
    int d0 = 2 * lane;
    int nt = lane >> 2, cg = lane & 3;
    float* sXw = sX + warp * 1280;
    float bc0 = sb[d0], bc1 = sb[d0 + 1];

    for (int t = fslot; t < NTILE; t += nslot) {
        int n0 = t * 128 + warp * 8;
        if (n0 >= Nn) continue;
        {
            int n = n0 + nt;
            bool v = n < Nn;
            const float4* xr = (const float4*)(x + (v ? n : 0) * Ff) + cg * 8;
#pragma unroll
            for (int q = 0; q < 8; q++) {
                float4 tv = v ? xr[q] : make_float4(0, 0, 0, 0);
                int c = cg * 32 + q * 4;
                sXw[(c + 0) * 10 + nt] = tv.x;
                sXw[(c + 1) * 10 + nt] = tv.y;
                sXw[(c + 2) * 10 + nt] = tv.z;
                sXw[(c + 3) * 10 + nt] = tv.w;
            }
        }
        __syncwarp();
        u64 acc[4][2];
#pragma unroll
        for (int p = 0; p < 4; p++) { acc[p][0] = 0ull; acc[p][1] = 0ull; }
#pragma unroll 4
        for (int k = 0; k < Ff; k++) {
            float2 w = *(const float2*)(sW + k * 64 + d0);
            u64 sw0 = splat2(w.x), sw1 = splat2(w.y);
            const u64* xp = (const u64*)(sXw + k * 10);
#pragma unroll
            for (int p = 0; p < 4; p++) {
                u64 xv = xp[p];
                acc[p][0] = ffma2(xv, sw0, acc[p][0]);
                acc[p][1] = ffma2(xv, sw1, acc[p][1]);
            }
        }
#pragma unroll
        for (int p = 0; p < 4; p++) {
            float2 a0 = unpk(acc[p][0]), a1 = unpk(acc[p][1]);
            int na = n0 + 2 * p, nb = na + 1;
            if (na < Nn) *(float2*)(out + na * 64 + d0) = make_float2(a0.x + bc0, a1.x + bc1);
            if (nb < Nn) *(float2*)(out + nb * 64 + d0) = make_float2(a0.y + bc0, a1.y + bc1);
        }
        __syncwarp();
    }
}

// ---------------- fused layer: mma.sync bf16 (3-product split) ----------------
// act tiles: 128 rows x 64 cols bf16, row stride 144 B (ldmatrix conflict-free)
#define SM_AGH 0
#define SM_AGL 18432
#define SM_HH  36864
#define SM_HL  55296
#define SM_CONV 73728        // relH 8K, relL 8K, rootH 8K, rootL 8K
#define SM_GRU  106496       // ihH 16K, ihL 16K, hhH 16K, hhL 16K, inH 8K, inL 8K, hnH 8K, hnL 8K
#define SM_BREL 204800
#define SM_BIH  205056
#define SM_BHH  205824
#define LAYER_SHM 206592

__global__ __launch_bounds__(512, 1) void k_layer(const float* __restrict__ in_base,
                                                  float* __restrict__ out_base,
                                                  int layer,
                                                  const float* __restrict__ brel_all,
                                                  const float* __restrict__ bih_all,
                                                  const float* __restrict__ bhh_all) {
    extern __shared__ unsigned char sm[];
    u32 smb = smem_u32(sm);
    int tid = threadIdx.x, warp = tid >> 5, lane = tid & 31;
    int f = blockIdx.x & 3;
    int fslot = blockIdx.x >> 2;
    int nslot = gridDim.x >> 2;
    int wl = f * NLl + layer;
    const float* in_state = in_base + f * Nn * Dd;
    float* out_state = out_base + f * Nn * Dd;
    const float* wfp = g_wcsr + f * Ee;

    {   // weights + biases -> smem
        const uint4* pc = (const uint4*)(g_pkconv + wl * 4096);
        uint4* dc = (uint4*)(sm + SM_CONV);
        for (int i = tid; i < 2048; i += 512) dc[i] = pc[i];
        const uint4* pg = (const uint4*)(g_pkgru + f * 12288);
        uint4* dg = (uint4*)(sm + SM_GRU);
        for (int i = tid; i < 6144; i += 512) dg[i] = pg[i];
        float* sb = (float*)(sm + SM_BREL);
        if (tid < 64) sb[tid] = brel_all[wl * 64 + tid];
        float* si = (float*)(sm + SM_BIH);
        float* shh = (float*)(sm + SM_BHH);
        if (tid < 192) { si[tid] = bih_all[f * 192 + tid]; shh[tid] = bhh_all[f * 192 + tid]; }
    }
    __syncthreads();

    int mt = warp >> 1, nh = warp & 1;
    int g = lane >> 2, s = lane & 3;
    u32 aoff = (u32)((mt * 16 + (lane & 15)) * 144 + (lane >> 4) * 16);
    int nl = tid >> 2, cg = tid & 3;
    const float* sbrel = (const float*)(sm + SM_BREL);
    const float* sbih  = (const float*)(sm + SM_BIH);
    const float* sbhh  = (const float*)(sm + SM_BHH);

    for (int t = fslot; t < NTILE; t += nslot) {
        int n0 = t * 128;

        // ---- stage: agg (fp32) + h -> bf16 hi/lo tiles ----
        {
            int gn = n0 + nl;
            bool v = gn < Nn;
            float hv[16], acc[16];
            const float4* hr = (const float4*)(in_state + (v ? gn : 0) * 64 + cg * 16);
#pragma unroll
            for (int q = 0; q < 4; q++) {
                float4 tv = v ? hr[q] : make_float4(0, 0, 0, 0);
                hv[4 * q] = tv.x; hv[4 * q + 1] = tv.y; hv[4 * q + 2] = tv.z; hv[4 * q + 3] = tv.w;
            }
#pragma unroll
            for (int ii = 0; ii < 16; ii++) acc[ii] = 0.f;
            if (v) {
                int beg = g_rowptr[gn], end = g_rowptr[gn + 1];
                for (int j = beg; j < end; j++) {
                    int sn = g_srcs[j];
                    float w = wfp[j];
                    const float4* sr = (const float4*)(in_state + sn * 64 + cg * 16);
#pragma unroll
                    for (int q = 0; q < 4; q++) {
                        float4 tv = sr[q];
                        acc[4 * q] += w * tv.x; acc[4 * q + 1] += w * tv.y;
                        acc[4 * q + 2] += w * tv.z; acc[4 * q + 3] += w * tv.w;
                    }
                }
            }
#pragma unroll
            for (int ii = 0; ii < 8; ii++) {
                int c = cg * 16 + 2 * ii;
                u32 off = (u32)(nl * 144 + c * 2);
                u32 hi, lo;
                split2(acc[2 * ii], acc[2 * ii + 1], hi, lo);
                *(u32*)(sm + SM_AGH + off) = hi;
                *(u32*)(sm + SM_AGL + off) = lo;
                split2(hv[2 * ii], hv[2 * ii + 1], hi, lo);
                *(u32*)(sm + SM_HH + off) = hi;
                *(u32*)(sm + SM_HL + off) = lo;
            }
        }
        __syncthreads();

        // ---- conv GEMM: D = agg@Wrel + h@Wroot (split) ----
        float accC[4][4];
#pragma unroll
        for (int a = 0; a < 4; a++)
#pragma unroll
            for (int b = 0; b < 4; b++) accC[a][b] = 0.f;
        {
            const u32 apair[6] = {SM_AGH, SM_AGL, SM_AGH, SM_HH, SM_HL, SM_HH};
            const u32 bpair[6] = {SM_CONV, SM_CONV, SM_CONV + 8192,
                                  SM_CONV + 16384, SM_CONV + 16384, SM_CONV + 24576};
#pragma unroll
            for (int p = 0; p < 6; p++) {
                u32 abase = smb + apair[p] + aoff;
                const uint2* breg = (const uint2*)(sm + bpair[p]);
#pragma unroll
                for (int ks = 0; ks < 4; ks++) {
                    uint4 a = ldm(abase + ks * 32);
#pragma unroll
                    for (int j = 0; j < 4; j++) {
                        uint2 b = breg[(ks * 8 + nh * 4 + j) * 32 + lane];
                        mmaf(accC[j], a, b);
                    }
                }
            }
        }
        __syncthreads();

        // ---- epilogue 1: m = relu(conv + brel) -> overwrite agg tiles ----
        {
#pragma unroll
            for (int j = 0; j < 4; j++) {
                int c = nh * 32 + j * 8 + 2 * s;
                u32 off = (u32)((mt * 16 + g) * 144 + c * 2);
                u32 hi, lo;
                float m0 = fmaxf(accC[j][0] + sbrel[c], 0.f);
                float m1 = fmaxf(accC[j][1] + sbrel[c + 1], 0.f);
                split2(m0, m1, hi, lo);
                *(u32*)(sm + SM_AGH + off) = hi;
                *(u32*)(sm + SM_AGL + off) = lo;
                m0 = fmaxf(accC[j][2] + sbrel[c], 0.f);
                m1 = fmaxf(accC[j][3] + sbrel[c + 1], 0.f);
                split2(m0, m1, hi, lo);
                *(u32*)(sm + SM_AGH + off + 8 * 144) = hi;
                *(u32*)(sm + SM_AGL + off + 8 * 144) = lo;
            }
        }
        __syncthreads();

        // ---- GRU GEMMs: rz (r+z fused with gi+gh sum), inn, hn ----
        float accRZ[8][4], accI[4][4], accH[4][4];
#pragma unroll
        for (int a = 0; a < 8; a++)
#pragma unroll
            for (int b = 0; b < 4; b++) accRZ[a][b] = 0.f;
#pragma unroll
        for (int a = 0; a < 4; a++)
#pragma unroll
            for (int b = 0; b < 4; b++) { accI[a][b] = 0.f; accH[a][b] = 0.f; }
        {
            const u32 apair[6] = {SM_AGH, SM_AGL, SM_AGH, SM_HH, SM_HL, SM_HH};
            const u32 bpair[6] = {SM_GRU, SM_GRU, SM_GRU + 16384,
                                  SM_GRU + 32768, SM_GRU + 32768, SM_GRU + 49152};
#pragma unroll
            for (int p = 0; p < 6; p++) {
                u32 abase = smb + apair[p] + aoff;
                const uint2* breg = (const uint2*)(sm + bpair[p]);
#pragma unroll
                for (int ks = 0; ks < 4; ks++) {
                    uint4 a = ldm(abase + ks * 32);
#pragma unroll
                    for (int j = 0; j < 8; j++) {
                        int ntg = (j < 4) ? (nh * 4 + j) : (8 + nh * 4 + j - 4);
                        uint2 b = breg[(ks * 16 + ntg) * 32 + lane];
                        mmaf(accRZ[j], a, b);
                    }
                }
            }
            const u32 apI[3] = {SM_AGH, SM_AGL, SM_AGH};
            const u32 bpI[3] = {SM_GRU + 65536, SM_GRU + 65536, SM_GRU + 73728};
#pragma unroll
            for (int p = 0; p < 3; p++) {
                u32 abase = smb + apI[p] + aoff;
                const uint2* breg = (const uint2*)(sm + bpI[p]);
#pragma unroll
                for (int ks = 0; ks < 4; ks++) {
                    uint4 a = ldm(abase + ks * 32);
#pragma unroll
                    for (int j = 0; j < 4; j++) {
                        uint2 b = breg[(ks * 8 + nh * 4 + j) * 32 + lane];
                        mmaf(accI[j], a, b);
                    }
                }
            }
            const u32 apH[3] = {SM_HH, SM_HL, SM_HH};
            const u32 bpH[3] = {SM_GRU + 81920, SM_GRU + 81920, SM_GRU + 90112};
#pragma unroll
            for (int p = 0; p < 3; p++) {
                u32 abase = smb + apH[p] + aoff;
                const uint2* breg = (const uint2*)(sm + bpH[p]);
#pragma unroll
                for (int ks = 0; ks < 4; ks++) {
                    uint4 a = ldm(abase + ks * 32);
#pragma unroll
                    for (int j = 0; j < 4; j++) {
                        uint2 b = breg[(ks * 8 + nh * 4 + j) * 32 + lane];
                        mmaf(accH[j], a, b);
                    }
                }
            }
        }

        // ---- epilogue 2: gates + blend + store (all in registers) ----
        {
#pragma unroll
            for (int j = 0; j < 4; j++) {
                int c = nh * 32 + j * 8 + 2 * s;
#pragma unroll
                for (int q = 0; q < 2; q++) {
                    int row = mt * 16 + g + q * 8;
                    int gn = n0 + row;
                    if (gn < Nn) {
                        float r0v = sigm(accRZ[j][2 * q]     + sbih[c]     + sbhh[c]);
                        float r1v = sigm(accRZ[j][2 * q + 1] + sbih[c + 1] + sbhh[c + 1]);
                        float z0v = sigm(accRZ[4 + j][2 * q]     + sbih[64 + c]     + sbhh[64 + c]);
                        float z1v = sigm(accRZ[4 + j][2 * q + 1] + sbih[64 + c + 1] + sbhh[64 + c + 1]);
                        float nn0 = tanh_f(accI[j][2 * q]     + sbih[128 + c]     + r0v * (accH[j][2 * q]     + sbhh[128 + c]));
                        float nn1 = tanh_f(accI[j][2 * q + 1] + sbih[128 + c + 1] + r1v * (accH[j][2 * q + 1] + sbhh[128 + c + 1]));
                        float2 hp = *(const float2*)(in_state + gn * 64 + c);
                        float o0 = (1.f - z0v) * nn0 + z0v * hp.x;
                        float o1 = (1.f - z1v) * nn1 + z1v * hp.y;
                        *(float2*)(out_state + gn * 64 + c) = make_float2(o0, o1);
                    }
                }
            }
        }
        __syncthreads();
    }
}

// ---------------- global mean pool ----------------
__global__ void k_pool(const float* __restrict__ feats, float* __restrict__ out) {
    int g = blockIdx.x, f = blockIdx.y, d = threadIdx.x;  // blockDim = 64
    int s = g_gstart[g], e = g_gstart[g + 1];
    const float* base = feats + f * Nn * Dd;
    float s0 = 0.f, s1 = 0.f, s2 = 0.f, s3 = 0.f;
    int i = s;
    for (; i + 3 < e; i += 4) {
        s0 += base[i * Dd + d];
        s1 += base[(i + 1) * Dd + d];
        s2 += base[(i + 2) * Dd + d];
        s3 += base[(i + 3) * Dd + d];
    }
    for (; i < e; i++) s0 += base[i * Dd + d];
    float sum = (s0 + s1) + (s2 + s3);
    int cnt = e - s;
    if (cnt < 1) cnt = 1;
    out[(f * Gg + g) * Dd + d] = sum / (float)cnt;
}

// ---------------- host ----------------
extern "C" void kernel_launch(void* const* d_in, const int* in_sizes, int n_in,
                              void* d_out, int out_size) {
    const float* x     = (const float*)d_in[0];
    const int*   ei    = (const int*)d_in[1];
    const float* att   = (const float*)d_in[2];
    const int*   batch = (const int*)d_in[3];
    const float* lin_W = (const float*)d_in[4];
    const float* lin_b = (const float*)d_in[5];
    const float* Wrel  = (const float*)d_in[6];
    const float* brel  = (const float*)d_in[7];
    const float* Wroot = (const float*)d_in[8];
    const float* Wih   = (const float*)d_in[9];
    const float* Whh   = (const float*)d_in[10];
    const float* bih   = (const float*)d_in[11];
    const float* bhh   = (const float*)d_in[12];

    float* out = (float*)d_out;
    float* feats = out + NFf * Gg * Dd;
    const int* srcp = ei;
    const int* dstp = ei + Ee;

    int sm = 148;
    cudaDeviceGetAttribute(&sm, cudaDevAttrMultiProcessorCount, 0);
    int grid = (sm / 4) * 4;
    if (grid < 4) grid = 4;

    cudaFuncSetAttribute(k_layer, cudaFuncAttributeMaxDynamicSharedMemorySize, LAYER_SHM);
    cudaFuncSetAttribute(k_lin, cudaFuncAttributeMaxDynamicSharedMemorySize, LIN_SHM);

    void *pa, *pb;
    cudaGetSymbolAddress(&pa, g_stateA);
    cudaGetSymbolAddress(&pb, g_stateB);
    float* A = (float*)pa;
    float* B = (float*)pb;

    const int NB = (Nn + 1023) / 1024;

    k_zero<<<(Nn + 255) / 256, 256>>>();
    k_hist<<<(Ee + 255) / 256, 256>>>(dstp, batch);
    k_scan1<<<NB, 1024>>>();
    k_scan2<<<1, 32>>>(NB);
    k_scan3<<<NB, 1024>>>();
    k_scatter<<<(Ee + 255) / 256, 256>>>(srcp, dstp);
    k_sortseg<<<(Nn + 127) / 128, 128>>>();
    k_buildw<<<(Ee + 255) / 256, 256>>>(att);
    k_gscan<<<1, 32>>>();
    k_pack<<<(98304 + 255) / 256, 256>>>(Wrel, Wroot, Wih, Whh);

    k_lin<<<grid, 512, LIN_SHM>>>(x, lin_W, lin_b, A);
    k_layer<<<grid, 512, LAYER_SHM>>>(A, B, 0, brel, bih, bhh);
    k_layer<<<grid, 512, LAYER_SHM>>>(B, A, 1, brel, bih, bhh);
    k_layer<<<grid, 512, LAYER_SHM>>>(A, feats, 2, brel, bih, bhh);
    k_pool<<<dim3(Gg, NFf), 64>>>(feats, out);
}